// round 12
// baseline (speedup 1.0000x reference)
#include <cuda_runtime.h>
#include <cuda_bf16.h>
#include <math_constants.h>

// Problem constants
#define NSEQ 2048
#define DMODEL 1024
#define NHEAD 16
#define HDIM 64
#define QKV_W (3 * DMODEL)   // 3072
#define QG_W  (4 * DMODEL)   // 4096

// ---------------------------------------------------------------------------
// Scratch (__device__ globals; no allocations allowed)
// ---------------------------------------------------------------------------
__device__ float g_qkv [NSEQ * QKV_W];     // q|k|v, fp32
__device__ float g_gate[NSEQ * DMODEL];    // sigmoid(x Wg^T + bg), fp32
__device__ float g_attn[NSEQ * DMODEL];    // attn_out * gate (tf32-rounded)
__device__ float g_xr  [NSEQ * DMODEL];    // tf32-rounded x
__device__ float g_wqg [QG_W * DMODEL];    // tf32-rounded [Wqkv ; Wgate]
__device__ float g_woutr[DMODEL * DMODEL]; // tf32-rounded Wout

__device__ __forceinline__ float rna_tf32(float x) {
    float y;
    asm("cvt.rna.tf32.f32 %0, %1;" : "=f"(y) : "f"(x));
    return y;
}

__device__ __forceinline__ void mma16n8k8(float* c, const unsigned* a, const unsigned* b)
{
    asm volatile(
        "mma.sync.aligned.m16n8k8.row.col.f32.tf32.tf32.f32 "
        "{%0,%1,%2,%3}, {%4,%5,%6,%7}, {%8,%9}, {%0,%1,%2,%3};\n"
        : "+f"(c[0]), "+f"(c[1]), "+f"(c[2]), "+f"(c[3])
        : "r"(a[0]), "r"(a[1]), "r"(a[2]), "r"(a[3]), "r"(b[0]), "r"(b[1]));
}

// ---------------------------------------------------------------------------
// Fast tf32 rounding pass: no branches, 4 independent coalesced float4/thread
// n4 must be a multiple of 4*blockDim (holds for all segments here).
// ---------------------------------------------------------------------------
__global__ void round_seg(const float4* __restrict__ in, float4* __restrict__ out)
{
    const int i0 = blockIdx.x * (blockDim.x * 4) + threadIdx.x;
    float4 v[4];
#pragma unroll
    for (int k = 0; k < 4; k++) v[k] = in[i0 + k * blockDim.x];
#pragma unroll
    for (int k = 0; k < 4; k++) {
        const float4 t = v[k];
        out[i0 + k * blockDim.x] =
            make_float4(rna_tf32(t.x), rna_tf32(t.y), rna_tf32(t.z), rna_tf32(t.w));
    }
}

// ---------------------------------------------------------------------------
// tf32 tensor-core GEMM (R10 proven): C = A @ Wcat^T + bias.
//   Blocks with col0 <  split -> C0 (row stride N0), bias0, no activation
//   Blocks with col0 >= split -> C1 (row stride N1), bias1, sigmoid
// 128x128 CTA tile, 4 warps (2x2 of 64x64), BK=16, double-buffered cp.async.
// Operands must be tf32-pre-rounded fp32.
// ---------------------------------------------------------------------------
#define BM 128
#define BN 128
#define BKT 16
#define LDSD 20

#define CP16(sm, gp) \
    asm volatile("cp.async.cg.shared.global [%0], [%1], 16;\n" :: "r"(sm), "l"(gp) : "memory")

__global__ __launch_bounds__(128, 2)
void mma_gemm(const float* __restrict__ A, const float* __restrict__ Wcat,
              const float* __restrict__ bias0, float* __restrict__ C0, int N0,
              const float* __restrict__ bias1, float* __restrict__ C1, int N1,
              int K, int split)
{
    __shared__ __align__(16) unsigned As[2][BM * LDSD];
    __shared__ __align__(16) unsigned Bs[2][BN * LDSD];

    const int tid  = threadIdx.x;
    const int lane = tid & 31;
    const int wid  = tid >> 5;
    const int wm   = wid & 1;          // 2 warps along M (64 rows each)
    const int wn   = wid >> 1;         // 2 warps along N (64 cols each)
    const int row0 = blockIdx.y * BM;
    const int col0 = blockIdx.x * BN;

    const int cpr = tid >> 2;          // 0..31
    const int cpc = (tid & 3) * 4;     // 0,4,8,12

    const float* Ag = A    + (size_t)(row0 + cpr) * K + cpc;
    const float* Wg = Wcat + (size_t)(col0 + cpr) * K + cpc;

    unsigned sA[2], sB[2];
    sA[0] = (unsigned)__cvta_generic_to_shared(&As[0][cpr * LDSD + cpc]);
    sA[1] = (unsigned)__cvta_generic_to_shared(&As[1][cpr * LDSD + cpc]);
    sB[0] = (unsigned)__cvta_generic_to_shared(&Bs[0][cpr * LDSD + cpc]);
    sB[1] = (unsigned)__cvta_generic_to_shared(&Bs[1][cpr * LDSD + cpc]);
    const unsigned soff32 = 32 * LDSD * 4;   // +32 rows in smem (bytes)
    const size_t   goff32 = (size_t)32 * K;  // +32 rows in gmem (elems)

    float acc[4][8][4];
#pragma unroll
    for (int mt = 0; mt < 4; mt++)
#pragma unroll
        for (int nt = 0; nt < 8; nt++)
#pragma unroll
            for (int i = 0; i < 4; i++) acc[mt][nt][i] = 0.0f;

    const int T = K / BKT;

    // prologue: tile 0 -> buf 0
#pragma unroll
    for (int r = 0; r < 4; r++) {
        CP16(sA[0] + r * soff32, Ag + r * goff32);
        CP16(sB[0] + r * soff32, Wg + r * goff32);
    }
    asm volatile("cp.async.commit_group;\n" ::: "memory");

    const int qk = lane & 3;
    const int qr = lane >> 2;

    for (int t = 0; t < T; t++) {
        const int buf = t & 1;
        if (t + 1 < T) {
            const int nb = buf ^ 1;
            const int k1 = (t + 1) * BKT;
#pragma unroll
            for (int r = 0; r < 4; r++) {
                CP16(sA[nb] + r * soff32, Ag + k1 + r * goff32);
                CP16(sB[nb] + r * soff32, Wg + k1 + r * goff32);
            }
        }
        asm volatile("cp.async.commit_group;\n" ::: "memory");
        asm volatile("cp.async.wait_group 1;\n" ::: "memory");
        __syncthreads();

        const unsigned* as = As[buf];
        const unsigned* bs = Bs[buf];
#pragma unroll
        for (int ks = 0; ks < 2; ks++) {
            unsigned bfr[8][2];
#pragma unroll
            for (int nt = 0; nt < 8; nt++) {
                const int n = wn * 64 + nt * 8 + qr;
                bfr[nt][0] = bs[n * LDSD + ks * 8 + qk];
                bfr[nt][1] = bs[n * LDSD + ks * 8 + qk + 4];
            }
            unsigned afr[4][4];
#pragma unroll
            for (int mt = 0; mt < 4; mt++) {
                const int m = wm * 64 + mt * 16 + qr;
                afr[mt][0] = as[m * LDSD + ks * 8 + qk];
                afr[mt][1] = as[(m + 8) * LDSD + ks * 8 + qk];
                afr[mt][2] = as[m * LDSD + ks * 8 + qk + 4];
                afr[mt][3] = as[(m + 8) * LDSD + ks * 8 + qk + 4];
            }
#pragma unroll
            for (int mt = 0; mt < 4; mt++)
#pragma unroll
                for (int nt = 0; nt < 8; nt++)
                    mma16n8k8(acc[mt][nt], afr[mt], bfr[nt]);
        }
        __syncthreads();
    }

    // epilogue: route to the right output (block-uniform)
    const int second = (col0 >= split);
    const float* bias = second ? bias1 : bias0;
    float* C  = second ? C1 : C0;
    const int Nn = second ? N1 : N0;
    const int cb = col0 - (second ? split : 0);

#pragma unroll
    for (int mt = 0; mt < 4; mt++) {
        const int r0 = row0 + wm * 64 + mt * 16 + qr;
#pragma unroll
        for (int nt = 0; nt < 8; nt++) {
            const int c = cb + wn * 64 + nt * 8 + qk * 2;
            const float2 bv = *(const float2*)&bias[c];
            float v0 = acc[mt][nt][0] + bv.x;
            float v1 = acc[mt][nt][1] + bv.y;
            float v2 = acc[mt][nt][2] + bv.x;
            float v3 = acc[mt][nt][3] + bv.y;
            if (second) {
                v0 = 1.0f / (1.0f + __expf(-v0));
                v1 = 1.0f / (1.0f + __expf(-v1));
                v2 = 1.0f / (1.0f + __expf(-v2));
                v3 = 1.0f / (1.0f + __expf(-v3));
            }
            *(float2*)&C[(size_t)r0 * Nn + c]       = make_float2(v0, v1);
            *(float2*)&C[(size_t)(r0 + 8) * Nn + c] = make_float2(v2, v3);
        }
    }
}

// ---------------------------------------------------------------------------
// Block-cooperative attention (R11 proven), fully tensor-core.
// Epilogue now rna-rounds the output so out-proj reads a valid tf32 A operand.
// ---------------------------------------------------------------------------
#define QT 16
#define NDENSE 65
#define WROWS 224
#define NTILES 28
#define KLD 68
#define SLD 228
#define ATTN_SMEM_BYTES 86080

__global__ __launch_bounds__(512, 2)
void attn_kernel(const float* __restrict__ qkv, const float* __restrict__ gate,
                 const float* __restrict__ pos_bias, const int* __restrict__ offsets,
                 float* __restrict__ attn_out, int NO)
{
    extern __shared__ __align__(16) float dsm[];
    float* Qsh  = dsm;                       // later: P@V partial buffer
    float* Ksh  = dsm + 1088;                // later: V window
    float* Ssh  = dsm + 16320;
    float* Gsh  = dsm + 19968;
    float* pb   = dsm + 21056;
    int*   goff = (int*)(dsm + 21136);
    int*   base = (int*)(dsm + 21216);
    int*   gidx = (int*)(dsm + 21296);

    const int tid = threadIdx.x;
    const int w = tid >> 5;
    const int l = tid & 31;
    const int h  = blockIdx.y;
    const int n0 = blockIdx.x * QT;

    if (tid < NO) {
        const int off = offsets[tid];
        goff[tid] = off;
        pb[tid]   = pos_bias[tid * NHEAD + h];
        base[tid] = (tid < NDENSE) ? (64 - off) : (80 + ((tid - NDENSE) << 4));
    }
    if (tid < WROWS) {
        int sn;
        if (tid < 80) sn = n0 - 64 + tid;
        else {
            const int g = (tid - 80) >> 4;
            const int s = (tid - 80) & 15;
            sn = (NDENSE + g < NO) ? (n0 - offsets[NDENSE + g] + s) : 0;
        }
        gidx[tid] = max(sn, 0);
    }
    __syncthreads();

    // stage K (rna), Q (rna, scaled), gate (raw)
    const float* Kg = qkv + DMODEL + h * HDIM;
    for (int i = tid; i < WROWS * 16; i += 512) {
        const int r  = i >> 4;
        const int c4 = (i & 15) << 2;
        const float4 v = *(const float4*)(Kg + (size_t)gidx[r] * QKV_W + c4);
        *(float4*)(Ksh + r * KLD + c4) =
            make_float4(rna_tf32(v.x), rna_tf32(v.y), rna_tf32(v.z), rna_tf32(v.w));
    }
    if (tid < 256) {
        const int r  = tid >> 4;
        const int c4 = (tid & 15) << 2;
        const float4 v = *(const float4*)(qkv + (size_t)(n0 + r) * QKV_W + h * HDIM + c4);
        *(float4*)(Qsh + r * KLD + c4) =
            make_float4(rna_tf32(v.x * 0.125f), rna_tf32(v.y * 0.125f),
                        rna_tf32(v.z * 0.125f), rna_tf32(v.w * 0.125f));
    } else {
        const int t2 = tid - 256;
        const int r  = t2 >> 4;
        const int c4 = (t2 & 15) << 2;
        *(float4*)(Gsh + r * KLD + c4) =
            *(const float4*)(gate + (size_t)(n0 + r) * DMODEL + h * HDIM + c4);
    }
    __syncthreads();

    // scores: 16 x 224 via mma; warp w handles n-tiles {w, w+16}
    const int qk = l & 3;
    const int qr = l >> 2;
    for (int nt = w; nt < NTILES; nt += 16) {
        float acc[4] = {0.0f, 0.0f, 0.0f, 0.0f};
#pragma unroll
        for (int ks = 0; ks < 8; ks++) {
            unsigned a[4], b[2];
            const float* qp = Qsh + qr * KLD + ks * 8 + qk;
            a[0] = __float_as_uint(qp[0]);
            a[1] = __float_as_uint(qp[8 * KLD]);
            a[2] = __float_as_uint(qp[4]);
            a[3] = __float_as_uint(qp[8 * KLD + 4]);
            const float* kp = Ksh + (nt * 8 + qr) * KLD + ks * 8 + qk;
            b[0] = __float_as_uint(kp[0]);
            b[1] = __float_as_uint(kp[4]);
            mma16n8k8(acc, a, b);
        }
        *(float2*)(Ssh + qr * SLD + nt * 8 + 2 * qk)       = make_float2(acc[0], acc[1]);
        *(float2*)(Ssh + (qr + 8) * SLD + nt * 8 + 2 * qk) = make_float2(acc[2], acc[3]);
    }
    __syncthreads();

    // restage V into Ksh (rna) — K data no longer needed
    const float* Vg = qkv + 2 * DMODEL + h * HDIM;
    for (int i = tid; i < WROWS * 16; i += 512) {
        const int r  = i >> 4;
        const int c4 = (i & 15) << 2;
        const float4 v = *(const float4*)(Vg + (size_t)gidx[r] * QKV_W + c4);
        *(float4*)(Ksh + r * KLD + c4) =
            make_float4(rna_tf32(v.x), rna_tf32(v.y), rna_tf32(v.z), rna_tf32(v.w));
    }

    // per-warp softmax on raw scores; warp w = query n0+w
    const int n = n0 + w;
    float* Srow = Ssh + w * SLD;
    float sloc[3];
    float m = -CUDART_INF_F;
#pragma unroll
    for (int j = 0; j < 3; j++) {
        const int o = l + 32 * j;
        float s = -CUDART_INF_F;
        if (o < NO && n - goff[o] >= 0)
            s = Srow[base[o] + w] + pb[o];
        sloc[j] = s;
        m = fmaxf(m, s);
    }
#pragma unroll
    for (int off = 16; off > 0; off >>= 1)
        m = fmaxf(m, __shfl_xor_sync(0xFFFFFFFFu, m, off));

    float ssum = 0.0f;
    float eloc[3];
#pragma unroll
    for (int j = 0; j < 3; j++) {
        const float e = (sloc[j] == -CUDART_INF_F) ? 0.0f : __expf(sloc[j] - m);
        eloc[j] = e;
        ssum += e;
    }
#pragma unroll
    for (int off = 16; off > 0; off >>= 1)
        ssum += __shfl_xor_sync(0xFFFFFFFFu, ssum, off);
    const float inv = 1.0f / ssum;

    // zero own score row, then scatter rna'd weights
#pragma unroll
    for (int j = 0; j < 7; j++) Srow[l + 32 * j] = 0.0f;
    __syncwarp();
#pragma unroll
    for (int j = 0; j < 3; j++) {
        const int o = l + 32 * j;
        if (o < NO) Srow[base[o] + w] = rna_tf32(eloc[j] * inv);
    }
    __syncthreads();   // V staged + all 16 rows weighted

    // P@V: out[16q][64d] = P[16][224] @ V[224][64]
    // warp w: n-tile = w&7 (8 dims), k-half = w>>3 (14 of 28 k-steps)
    const int nt2 = w & 7;
    const int kh  = w >> 3;
    float facc[4] = {0.0f, 0.0f, 0.0f, 0.0f};
    for (int kk = kh * 14; kk < kh * 14 + 14; kk++) {
        unsigned a[4], b[2];
        const float* pp = Ssh + qr * SLD + kk * 8 + qk;
        a[0] = __float_as_uint(pp[0]);
        a[1] = __float_as_uint(pp[8 * SLD]);
        a[2] = __float_as_uint(pp[4]);
        a[3] = __float_as_uint(pp[8 * SLD + 4]);
        b[0] = __float_as_uint(Ksh[(kk * 8 + qk) * KLD + nt2 * 8 + qr]);
        b[1] = __float_as_uint(Ksh[(kk * 8 + qk + 4) * KLD + nt2 * 8 + qr]);
        mma16n8k8(facc, a, b);
    }

    // reduce the two k-halves through Qsh (free), gate-multiply (rna), store
    if (kh == 1) {
        *(float2*)(Qsh + qr * KLD + nt2 * 8 + 2 * qk)       = make_float2(facc[0], facc[1]);
        *(float2*)(Qsh + (qr + 8) * KLD + nt2 * 8 + 2 * qk) = make_float2(facc[2], facc[3]);
    }
    __syncthreads();
    if (kh == 0) {
        const int cc = nt2 * 8 + 2 * qk;
        const float2 p0 = *(const float2*)(Qsh + qr * KLD + cc);
        const float2 p1 = *(const float2*)(Qsh + (qr + 8) * KLD + cc);
        const float2 g0 = *(const float2*)(Gsh + qr * KLD + cc);
        const float2 g1 = *(const float2*)(Gsh + (qr + 8) * KLD + cc);
        float2 r0, r1;
        r0.x = rna_tf32((facc[0] + p0.x) * g0.x);
        r0.y = rna_tf32((facc[1] + p0.y) * g0.y);
        r1.x = rna_tf32((facc[2] + p1.x) * g1.x);
        r1.y = rna_tf32((facc[3] + p1.y) * g1.y);
        *(float2*)(attn_out + (size_t)(n0 + qr) * DMODEL + h * HDIM + cc)     = r0;
        *(float2*)(attn_out + (size_t)(n0 + qr + 8) * DMODEL + h * HDIM + cc) = r1;
    }
}

// ---------------------------------------------------------------------------
// Launch
// ---------------------------------------------------------------------------
extern "C" void kernel_launch(void* const* d_in, const int* in_sizes, int n_in,
                              void* d_out, int out_size)
{
    const float* x        = (const float*)d_in[0];
    const float* Wqkv     = (const float*)d_in[1];
    const float* bqkv     = (const float*)d_in[2];
    const float* Wgate    = (const float*)d_in[3];
    const float* bgate    = (const float*)d_in[4];
    const float* Wout     = (const float*)d_in[5];
    const float* bout     = (const float*)d_in[6];
    const float* pos_bias = (const float*)d_in[7];
    const int*   offsets  = (const int*)d_in[8];
    const int NO = in_sizes[8];

    float *qkv_p, *gate_p, *attn_p, *xr_p, *wqg_p, *woutr_p;
    cudaGetSymbolAddress((void**)&qkv_p,   g_qkv);
    cudaGetSymbolAddress((void**)&gate_p,  g_gate);
    cudaGetSymbolAddress((void**)&attn_p,  g_attn);
    cudaGetSymbolAddress((void**)&xr_p,    g_xr);
    cudaGetSymbolAddress((void**)&wqg_p,   g_wqg);
    cudaGetSymbolAddress((void**)&woutr_p, g_woutr);

    cudaFuncSetAttribute(attn_kernel, cudaFuncAttributeMaxDynamicSharedMemorySize,
                         ATTN_SMEM_BYTES);

    // 0) tf32-round GEMM operands (branch-free, MLP=4 per thread)
    round_seg<<<(NSEQ  * DMODEL / 4) / 1024, 256>>>((const float4*)x,     (float4*)xr_p);
    round_seg<<<(QKV_W * DMODEL / 4) / 1024, 256>>>((const float4*)Wqkv,  (float4*)wqg_p);
    round_seg<<<(DMODEL * DMODEL / 4) / 1024, 256>>>((const float4*)Wgate,
                                                     (float4*)(wqg_p + (size_t)QKV_W * DMODEL));
    round_seg<<<(DMODEL * DMODEL / 4) / 1024, 256>>>((const float4*)Wout,  (float4*)woutr_p);

    // 1) fused: qkv = x@Wqkv^T+bqkv  AND  gate = sigmoid(x@Wgate^T+bgate)
    mma_gemm<<<dim3(QG_W / BN, NSEQ / BM), 128>>>(
        xr_p, wqg_p,
        bqkv,  qkv_p,  QKV_W,
        bgate, gate_p, DMODEL,
        DMODEL, QKV_W);

    // 2) attention + gate multiply (tf32-rounded output)
    attn_kernel<<<dim3(NSEQ / QT, NHEAD), 512, ATTN_SMEM_BYTES>>>(
        qkv_p, gate_p, pos_bias, offsets, attn_p, NO);

    // 3) out = (attn*gate) @ Wout^T + bout
    mma_gemm<<<dim3(DMODEL / BN, NSEQ / BM), 128>>>(
        attn_p, woutr_p,
        bout, (float*)d_out, DMODEL,
        bout, (float*)d_out, DMODEL,
        DMODEL, 1 << 30);
}

// round 13
// speedup vs baseline: 1.0127x; 1.0127x over previous
#include <cuda_runtime.h>
#include <cuda_bf16.h>
#include <math_constants.h>

// Problem constants
#define NSEQ 2048
#define DMODEL 1024
#define NHEAD 16
#define HDIM 64
#define QKV_W (3 * DMODEL)   // 3072
#define QG_W  (4 * DMODEL)   // 4096

// ---------------------------------------------------------------------------
// Scratch (__device__ globals; no allocations allowed)
// ---------------------------------------------------------------------------
__device__ float g_qkv [NSEQ * QKV_W];     // q|k|v, fp32
__device__ float g_gate[NSEQ * DMODEL];    // sigmoid(x Wg^T + bg), fp32
__device__ float g_attn[NSEQ * DMODEL];    // attn_out * gate (tf32-rounded)
__device__ float g_xr  [NSEQ * DMODEL];    // tf32-rounded x
__device__ float g_wqg [QG_W * DMODEL];    // tf32-rounded [Wqkv ; Wgate]
__device__ float g_woutr[DMODEL * DMODEL]; // tf32-rounded Wout

__device__ __forceinline__ float rna_tf32(float x) {
    float y;
    asm("cvt.rna.tf32.f32 %0, %1;" : "=f"(y) : "f"(x));
    return y;
}

__device__ __forceinline__ void mma16n8k8(float* c, const unsigned* a, const unsigned* b)
{
    asm volatile(
        "mma.sync.aligned.m16n8k8.row.col.f32.tf32.tf32.f32 "
        "{%0,%1,%2,%3}, {%4,%5,%6,%7}, {%8,%9}, {%0,%1,%2,%3};\n"
        : "+f"(c[0]), "+f"(c[1]), "+f"(c[2]), "+f"(c[3])
        : "r"(a[0]), "r"(a[1]), "r"(a[2]), "r"(a[3]), "r"(b[0]), "r"(b[1]));
}

#define CP16(sm, gp) \
    asm volatile("cp.async.cg.shared.global [%0], [%1], 16;\n" :: "r"(sm), "l"(gp) : "memory")
#define CP_COMMIT() asm volatile("cp.async.commit_group;\n" ::: "memory")
#define CP_WAIT1()  asm volatile("cp.async.wait_group 1;\n" ::: "memory")

// ---------------------------------------------------------------------------
// Merged tf32 rounding: x | Wqkv | Wgate | Wout in ONE launch, 2 float4/thread
// ---------------------------------------------------------------------------
#define RS0 (NSEQ * DMODEL / 4)      // 524288
#define RS1 (QKV_W * DMODEL / 4)     // 786432
#define RS2 (DMODEL * DMODEL / 4)    // 262144
#define RS3 (DMODEL * DMODEL / 4)    // 262144
#define RTOT (RS0 + RS1 + RS2 + RS3) // 1835008
#define RBLK 3584                    // RTOT / (256*2)

__global__ void round_all(const float4* __restrict__ x,  float4* __restrict__ xr,
                          const float4* __restrict__ wq, float4* __restrict__ wqr,
                          const float4* __restrict__ wg, float4* __restrict__ wgr,
                          const float4* __restrict__ wo, float4* __restrict__ wor)
{
    const int i0 = blockIdx.x * 512 + threadIdx.x;
#pragma unroll
    for (int k = 0; k < 2; k++) {
        int j = i0 + k * 256;
        const float4* src; float4* dst;
        if (j < RS0)               { src = x;  dst = xr; }
        else if ((j -= RS0) < RS1) { src = wq; dst = wqr; }
        else if ((j -= RS1) < RS2) { src = wg; dst = wgr; }
        else { j -= RS2;             src = wo; dst = wor; }
        const float4 v = src[j];
        dst[j] = make_float4(rna_tf32(v.x), rna_tf32(v.y),
                             rna_tf32(v.z), rna_tf32(v.w));
    }
}

// ---------------------------------------------------------------------------
// Fused GEMM (qkv + gate): 256x128 CTA tile, 8 warps (4x2 of 64x64), BK=16,
// double-buffered cp.async. Blocks with col0 < split -> C0/bias0 (linear),
// else C1/bias1 (sigmoid). Dynamic smem: 2 * (256+128)*20 words = 61440 B.
// ---------------------------------------------------------------------------
#define GBM 256
#define GBN 128
#define BKT 16
#define LDSD 20
#define BIG_STGW ((GBM + GBN) * LDSD)          // 7680 words
#define BIG_SMEM_BYTES (2 * BIG_STGW * 4)      // 61440

__global__ __launch_bounds__(256, 1)
void gemm_big(const float* __restrict__ A, const float* __restrict__ Wcat,
              const float* __restrict__ bias0, float* __restrict__ C0, int N0,
              const float* __restrict__ bias1, float* __restrict__ C1, int N1,
              int K, int split)
{
    extern __shared__ __align__(16) unsigned bsm[];

    const int tid  = threadIdx.x;
    const int lane = tid & 31;
    const int wid  = tid >> 5;
    const int wm   = wid & 3;          // 4 warps along M (64 rows each)
    const int wn   = wid >> 2;         // 2 warps along N (64 cols each)
    const int row0 = blockIdx.y * GBM;
    const int col0 = blockIdx.x * GBN;

    const int cpr = tid >> 2;          // 0..63
    const int cpc = (tid & 3) * 4;     // 0,4,8,12

    const float* Ag = A    + (size_t)(row0 + cpr) * K + cpc;
    const float* Wg = Wcat + (size_t)(col0 + cpr) * K + cpc;

    const unsigned shb = (unsigned)__cvta_generic_to_shared(bsm);
    const unsigned aoff = (cpr * LDSD + cpc) * 4;
    const unsigned boff = (GBM * LDSD + cpr * LDSD + cpc) * 4;
    const unsigned soff64 = 64 * LDSD * 4;
    const size_t   goff64 = (size_t)64 * K;

    float acc[4][8][4];
#pragma unroll
    for (int mt = 0; mt < 4; mt++)
#pragma unroll
        for (int nt = 0; nt < 8; nt++)
#pragma unroll
            for (int i = 0; i < 4; i++) acc[mt][nt][i] = 0.0f;

    const int T = K / BKT;

    // prologue: tile 0 -> buf 0
#pragma unroll
    for (int r = 0; r < 4; r++) CP16(shb + aoff + r * soff64, Ag + r * goff64);
#pragma unroll
    for (int r = 0; r < 2; r++) CP16(shb + boff + r * soff64, Wg + r * goff64);
    CP_COMMIT();

    const int qk = lane & 3;
    const int qr = lane >> 2;

    for (int t = 0; t < T; t++) {
        const int buf = t & 1;
        if (t + 1 < T) {
            const unsigned nb = (buf ^ 1) * BIG_STGW * 4;
            const int k1 = (t + 1) * BKT;
#pragma unroll
            for (int r = 0; r < 4; r++)
                CP16(shb + nb + aoff + r * soff64, Ag + k1 + r * goff64);
#pragma unroll
            for (int r = 0; r < 2; r++)
                CP16(shb + nb + boff + r * soff64, Wg + k1 + r * goff64);
        }
        CP_COMMIT();
        CP_WAIT1();
        __syncthreads();

        const unsigned* as = bsm + buf * BIG_STGW;
        const unsigned* bs = as + GBM * LDSD;
#pragma unroll
        for (int ks = 0; ks < 2; ks++) {
            unsigned bfr[8][2];
#pragma unroll
            for (int nt = 0; nt < 8; nt++) {
                const int n = wn * 64 + nt * 8 + qr;
                bfr[nt][0] = bs[n * LDSD + ks * 8 + qk];
                bfr[nt][1] = bs[n * LDSD + ks * 8 + qk + 4];
            }
            unsigned afr[4][4];
#pragma unroll
            for (int mt = 0; mt < 4; mt++) {
                const int m = wm * 64 + mt * 16 + qr;
                afr[mt][0] = as[m * LDSD + ks * 8 + qk];
                afr[mt][1] = as[(m + 8) * LDSD + ks * 8 + qk];
                afr[mt][2] = as[m * LDSD + ks * 8 + qk + 4];
                afr[mt][3] = as[(m + 8) * LDSD + ks * 8 + qk + 4];
            }
#pragma unroll
            for (int mt = 0; mt < 4; mt++)
#pragma unroll
                for (int nt = 0; nt < 8; nt++)
                    mma16n8k8(acc[mt][nt], afr[mt], bfr[nt]);
        }
        __syncthreads();
    }

    const int second = (col0 >= split);
    const float* bias = second ? bias1 : bias0;
    float* C  = second ? C1 : C0;
    const int Nn = second ? N1 : N0;
    const int cb = col0 - (second ? split : 0);

#pragma unroll
    for (int mt = 0; mt < 4; mt++) {
        const int r0 = row0 + wm * 64 + mt * 16 + qr;
#pragma unroll
        for (int nt = 0; nt < 8; nt++) {
            const int c = cb + wn * 64 + nt * 8 + qk * 2;
            const float2 bv = *(const float2*)&bias[c];
            float v0 = acc[mt][nt][0] + bv.x;
            float v1 = acc[mt][nt][1] + bv.y;
            float v2 = acc[mt][nt][2] + bv.x;
            float v3 = acc[mt][nt][3] + bv.y;
            if (second) {
                v0 = 1.0f / (1.0f + __expf(-v0));
                v1 = 1.0f / (1.0f + __expf(-v1));
                v2 = 1.0f / (1.0f + __expf(-v2));
                v3 = 1.0f / (1.0f + __expf(-v3));
            }
            *(float2*)&C[(size_t)r0 * Nn + c]       = make_float2(v0, v1);
            *(float2*)&C[(size_t)(r0 + 8) * Nn + c] = make_float2(v2, v3);
        }
    }
}

// ---------------------------------------------------------------------------
// Out-projection GEMM: 64x128 CTA tile, 4 warps (2x2 of 32x64), BK=16,
// double-buffered cp.async. grid=256 -> ~2 warps/SMSP resident.
// ---------------------------------------------------------------------------
#define SBM 64
#define SBN 128

__global__ __launch_bounds__(128, 3)
void gemm_small(const float* __restrict__ A, const float* __restrict__ W,
                const float* __restrict__ bias, float* __restrict__ C, int Nn,
                int K)
{
    __shared__ __align__(16) unsigned As[2][SBM * LDSD];
    __shared__ __align__(16) unsigned Bs[2][SBN * LDSD];

    const int tid  = threadIdx.x;
    const int lane = tid & 31;
    const int wid  = tid >> 5;
    const int wm   = wid & 1;          // 2 warps along M (32 rows each)
    const int wn   = wid >> 1;         // 2 warps along N (64 cols each)
    const int row0 = blockIdx.y * SBM;
    const int col0 = blockIdx.x * SBN;

    const int cpr = tid >> 2;          // 0..31
    const int cpc = (tid & 3) * 4;

    const float* Ag = A + (size_t)(row0 + cpr) * K + cpc;
    const float* Wg = W + (size_t)(col0 + cpr) * K + cpc;

    unsigned sA[2], sB[2];
    sA[0] = (unsigned)__cvta_generic_to_shared(&As[0][cpr * LDSD + cpc]);
    sA[1] = (unsigned)__cvta_generic_to_shared(&As[1][cpr * LDSD + cpc]);
    sB[0] = (unsigned)__cvta_generic_to_shared(&Bs[0][cpr * LDSD + cpc]);
    sB[1] = (unsigned)__cvta_generic_to_shared(&Bs[1][cpr * LDSD + cpc]);
    const unsigned soff32 = 32 * LDSD * 4;
    const size_t   goff32 = (size_t)32 * K;

    float acc[2][8][4];
#pragma unroll
    for (int mt = 0; mt < 2; mt++)
#pragma unroll
        for (int nt = 0; nt < 8; nt++)
#pragma unroll
            for (int i = 0; i < 4; i++) acc[mt][nt][i] = 0.0f;

    const int T = K / BKT;

#pragma unroll
    for (int r = 0; r < 2; r++) CP16(sA[0] + r * soff32, Ag + r * goff32);
#pragma unroll
    for (int r = 0; r < 4; r++) CP16(sB[0] + r * soff32, Wg + r * goff32);
    CP_COMMIT();

    const int qk = lane & 3;
    const int qr = lane >> 2;

    for (int t = 0; t < T; t++) {
        const int buf = t & 1;
        if (t + 1 < T) {
            const int nb = buf ^ 1;
            const int k1 = (t + 1) * BKT;
#pragma unroll
            for (int r = 0; r < 2; r++) CP16(sA[nb] + r * soff32, Ag + k1 + r * goff32);
#pragma unroll
            for (int r = 0; r < 4; r++) CP16(sB[nb] + r * soff32, Wg + k1 + r * goff32);
        }
        CP_COMMIT();
        CP_WAIT1();
        __syncthreads();

        const unsigned* as = As[buf];
        const unsigned* bs = Bs[buf];
#pragma unroll
        for (int ks = 0; ks < 2; ks++) {
            unsigned bfr[8][2];
#pragma unroll
            for (int nt = 0; nt < 8; nt++) {
                const int n = wn * 64 + nt * 8 + qr;
                bfr[nt][0] = bs[n * LDSD + ks * 8 + qk];
                bfr[nt][1] = bs[n * LDSD + ks * 8 + qk + 4];
            }
            unsigned afr[2][4];
#pragma unroll
            for (int mt = 0; mt < 2; mt++) {
                const int m = wm * 32 + mt * 16 + qr;
                afr[mt][0] = as[m * LDSD + ks * 8 + qk];
                afr[mt][1] = as[(m + 8) * LDSD + ks * 8 + qk];
                afr[mt][2] = as[m * LDSD + ks * 8 + qk + 4];
                afr[mt][3] = as[(m + 8) * LDSD + ks * 8 + qk + 4];
            }
#pragma unroll
            for (int mt = 0; mt < 2; mt++)
#pragma unroll
                for (int nt = 0; nt < 8; nt++)
                    mma16n8k8(acc[mt][nt], afr[mt], bfr[nt]);
        }
        __syncthreads();
    }

#pragma unroll
    for (int mt = 0; mt < 2; mt++) {
        const int r0 = row0 + wm * 32 + mt * 16 + qr;
#pragma unroll
        for (int nt = 0; nt < 8; nt++) {
            const int c = col0 + wn * 64 + nt * 8 + qk * 2;
            const float2 bv = *(const float2*)&bias[c];
            *(float2*)&C[(size_t)r0 * Nn + c] =
                make_float2(acc[mt][nt][0] + bv.x, acc[mt][nt][1] + bv.y);
            *(float2*)&C[(size_t)(r0 + 8) * Nn + c] =
                make_float2(acc[mt][nt][2] + bv.x, acc[mt][nt][3] + bv.y);
        }
    }
}

// ---------------------------------------------------------------------------
// Block-cooperative attention (R11/R12 proven), fully tensor-core.
// ---------------------------------------------------------------------------
#define QT 16
#define NDENSE 65
#define WROWS 224
#define NTILES 28
#define KLD 68
#define SLD 228
#define ATTN_SMEM_BYTES 86080

__global__ __launch_bounds__(512, 2)
void attn_kernel(const float* __restrict__ qkv, const float* __restrict__ gate,
                 const float* __restrict__ pos_bias, const int* __restrict__ offsets,
                 float* __restrict__ attn_out, int NO)
{
    extern __shared__ __align__(16) float dsm[];
    float* Qsh  = dsm;
    float* Ksh  = dsm + 1088;
    float* Ssh  = dsm + 16320;
    float* Gsh  = dsm + 19968;
    float* pb   = dsm + 21056;
    int*   goff = (int*)(dsm + 21136);
    int*   base = (int*)(dsm + 21216);
    int*   gidx = (int*)(dsm + 21296);

    const int tid = threadIdx.x;
    const int w = tid >> 5;
    const int l = tid & 31;
    const int h  = blockIdx.y;
    const int n0 = blockIdx.x * QT;

    if (tid < NO) {
        const int off = offsets[tid];
        goff[tid] = off;
        pb[tid]   = pos_bias[tid * NHEAD + h];
        base[tid] = (tid < NDENSE) ? (64 - off) : (80 + ((tid - NDENSE) << 4));
    }
    if (tid < WROWS) {
        int sn;
        if (tid < 80) sn = n0 - 64 + tid;
        else {
            const int g = (tid - 80) >> 4;
            const int s = (tid - 80) & 15;
            sn = (NDENSE + g < NO) ? (n0 - offsets[NDENSE + g] + s) : 0;
        }
        gidx[tid] = max(sn, 0);
    }
    __syncthreads();

    const float* Kg = qkv + DMODEL + h * HDIM;
    for (int i = tid; i < WROWS * 16; i += 512) {
        const int r  = i >> 4;
        const int c4 = (i & 15) << 2;
        const float4 v = *(const float4*)(Kg + (size_t)gidx[r] * QKV_W + c4);
        *(float4*)(Ksh + r * KLD + c4) =
            make_float4(rna_tf32(v.x), rna_tf32(v.y), rna_tf32(v.z), rna_tf32(v.w));
    }
    if (tid < 256) {
        const int r  = tid >> 4;
        const int c4 = (tid & 15) << 2;
        const float4 v = *(const float4*)(qkv + (size_t)(n0 + r) * QKV_W + h * HDIM + c4);
        *(float4*)(Qsh + r * KLD + c4) =
            make_float4(rna_tf32(v.x * 0.125f), rna_tf32(v.y * 0.125f),
                        rna_tf32(v.z * 0.125f), rna_tf32(v.w * 0.125f));
    } else {
        const int t2 = tid - 256;
        const int r  = t2 >> 4;
        const int c4 = (t2 & 15) << 2;
        *(float4*)(Gsh + r * KLD + c4) =
            *(const float4*)(gate + (size_t)(n0 + r) * DMODEL + h * HDIM + c4);
    }
    __syncthreads();

    const int qk = l & 3;
    const int qr = l >> 2;
    for (int nt = w; nt < NTILES; nt += 16) {
        float acc[4] = {0.0f, 0.0f, 0.0f, 0.0f};
#pragma unroll
        for (int ks = 0; ks < 8; ks++) {
            unsigned a[4], b[2];
            const float* qp = Qsh + qr * KLD + ks * 8 + qk;
            a[0] = __float_as_uint(qp[0]);
            a[1] = __float_as_uint(qp[8 * KLD]);
            a[2] = __float_as_uint(qp[4]);
            a[3] = __float_as_uint(qp[8 * KLD + 4]);
            const float* kp = Ksh + (nt * 8 + qr) * KLD + ks * 8 + qk;
            b[0] = __float_as_uint(kp[0]);
            b[1] = __float_as_uint(kp[4]);
            mma16n8k8(acc, a, b);
        }
        *(float2*)(Ssh + qr * SLD + nt * 8 + 2 * qk)       = make_float2(acc[0], acc[1]);
        *(float2*)(Ssh + (qr + 8) * SLD + nt * 8 + 2 * qk) = make_float2(acc[2], acc[3]);
    }
    __syncthreads();

    const float* Vg = qkv + 2 * DMODEL + h * HDIM;
    for (int i = tid; i < WROWS * 16; i += 512) {
        const int r  = i >> 4;
        const int c4 = (i & 15) << 2;
        const float4 v = *(const float4*)(Vg + (size_t)gidx[r] * QKV_W + c4);
        *(float4*)(Ksh + r * KLD + c4) =
            make_float4(rna_tf32(v.x), rna_tf32(v.y), rna_tf32(v.z), rna_tf32(v.w));
    }

    const int n = n0 + w;
    float* Srow = Ssh + w * SLD;
    float sloc[3];
    float m = -CUDART_INF_F;
#pragma unroll
    for (int j = 0; j < 3; j++) {
        const int o = l + 32 * j;
        float s = -CUDART_INF_F;
        if (o < NO && n - goff[o] >= 0)
            s = Srow[base[o] + w] + pb[o];
        sloc[j] = s;
        m = fmaxf(m, s);
    }
#pragma unroll
    for (int off = 16; off > 0; off >>= 1)
        m = fmaxf(m, __shfl_xor_sync(0xFFFFFFFFu, m, off));

    float ssum = 0.0f;
    float eloc[3];
#pragma unroll
    for (int j = 0; j < 3; j++) {
        const float e = (sloc[j] == -CUDART_INF_F) ? 0.0f : __expf(sloc[j] - m);
        eloc[j] = e;
        ssum += e;
    }
#pragma unroll
    for (int off = 16; off > 0; off >>= 1)
        ssum += __shfl_xor_sync(0xFFFFFFFFu, ssum, off);
    const float inv = 1.0f / ssum;

#pragma unroll
    for (int j = 0; j < 7; j++) Srow[l + 32 * j] = 0.0f;
    __syncwarp();
#pragma unroll
    for (int j = 0; j < 3; j++) {
        const int o = l + 32 * j;
        if (o < NO) Srow[base[o] + w] = rna_tf32(eloc[j] * inv);
    }
    __syncthreads();

    const int nt2 = w & 7;
    const int kh  = w >> 3;
    float facc[4] = {0.0f, 0.0f, 0.0f, 0.0f};
    for (int kk = kh * 14; kk < kh * 14 + 14; kk++) {
        unsigned a[4], b[2];
        const float* pp = Ssh + qr * SLD + kk * 8 + qk;
        a[0] = __float_as_uint(pp[0]);
        a[1] = __float_as_uint(pp[8 * SLD]);
        a[2] = __float_as_uint(pp[4]);
        a[3] = __float_as_uint(pp[8 * SLD + 4]);
        b[0] = __float_as_uint(Ksh[(kk * 8 + qk) * KLD + nt2 * 8 + qr]);
        b[1] = __float_as_uint(Ksh[(kk * 8 + qk + 4) * KLD + nt2 * 8 + qr]);
        mma16n8k8(facc, a, b);
    }

    if (kh == 1) {
        *(float2*)(Qsh + qr * KLD + nt2 * 8 + 2 * qk)       = make_float2(facc[0], facc[1]);
        *(float2*)(Qsh + (qr + 8) * KLD + nt2 * 8 + 2 * qk) = make_float2(facc[2], facc[3]);
    }
    __syncthreads();
    if (kh == 0) {
        const int cc = nt2 * 8 + 2 * qk;
        const float2 p0 = *(const float2*)(Qsh + qr * KLD + cc);
        const float2 p1 = *(const float2*)(Qsh + (qr + 8) * KLD + cc);
        const float2 g0 = *(const float2*)(Gsh + qr * KLD + cc);
        const float2 g1 = *(const float2*)(Gsh + (qr + 8) * KLD + cc);
        float2 r0, r1;
        r0.x = rna_tf32((facc[0] + p0.x) * g0.x);
        r0.y = rna_tf32((facc[1] + p0.y) * g0.y);
        r1.x = rna_tf32((facc[2] + p1.x) * g1.x);
        r1.y = rna_tf32((facc[3] + p1.y) * g1.y);
        *(float2*)(attn_out + (size_t)(n0 + qr) * DMODEL + h * HDIM + cc)     = r0;
        *(float2*)(attn_out + (size_t)(n0 + qr + 8) * DMODEL + h * HDIM + cc) = r1;
    }
}

// ---------------------------------------------------------------------------
// Launch
// ---------------------------------------------------------------------------
extern "C" void kernel_launch(void* const* d_in, const int* in_sizes, int n_in,
                              void* d_out, int out_size)
{
    const float* x        = (const float*)d_in[0];
    const float* Wqkv     = (const float*)d_in[1];
    const float* bqkv     = (const float*)d_in[2];
    const float* Wgate    = (const float*)d_in[3];
    const float* bgate    = (const float*)d_in[4];
    const float* Wout     = (const float*)d_in[5];
    const float* bout     = (const float*)d_in[6];
    const float* pos_bias = (const float*)d_in[7];
    const int*   offsets  = (const int*)d_in[8];
    const int NO = in_sizes[8];

    float *qkv_p, *gate_p, *attn_p, *xr_p, *wqg_p, *woutr_p;
    cudaGetSymbolAddress((void**)&qkv_p,   g_qkv);
    cudaGetSymbolAddress((void**)&gate_p,  g_gate);
    cudaGetSymbolAddress((void**)&attn_p,  g_attn);
    cudaGetSymbolAddress((void**)&xr_p,    g_xr);
    cudaGetSymbolAddress((void**)&wqg_p,   g_wqg);
    cudaGetSymbolAddress((void**)&woutr_p, g_woutr);

    cudaFuncSetAttribute(gemm_big, cudaFuncAttributeMaxDynamicSharedMemorySize,
                         BIG_SMEM_BYTES);
    cudaFuncSetAttribute(attn_kernel, cudaFuncAttributeMaxDynamicSharedMemorySize,
                         ATTN_SMEM_BYTES);

    // 0) tf32-round all GEMM operands in ONE launch
    round_all<<<RBLK, 256>>>((const float4*)x,     (float4*)xr_p,
                             (const float4*)Wqkv,  (float4*)wqg_p,
                             (const float4*)Wgate, (float4*)(wqg_p + (size_t)QKV_W * DMODEL),
                             (const float4*)Wout,  (float4*)woutr_p);

    // 1) fused: qkv = x@Wqkv^T+bqkv  AND  gate = sigmoid(x@Wgate^T+bgate)
    gemm_big<<<dim3(QG_W / GBN, NSEQ / GBM), 256, BIG_SMEM_BYTES>>>(
        xr_p, wqg_p,
        bqkv,  qkv_p,  QKV_W,
        bgate, gate_p, DMODEL,
        DMODEL, QKV_W);

    // 2) attention + gate multiply (tf32-rounded output)
    attn_kernel<<<dim3(NSEQ / QT, NHEAD), 512, ATTN_SMEM_BYTES>>>(
        qkv_p, gate_p, pos_bias, offsets, attn_p, NO);

    // 3) out = (attn*gate) @ Wout^T + bout
    gemm_small<<<dim3(DMODEL / SBN, NSEQ / SBM), 128>>>(
        attn_p, woutr_p, bout, (float*)d_out, DMODEL, DMODEL);
}

// round 16
// speedup vs baseline: 1.4268x; 1.4089x over previous
#include <cuda_runtime.h>
#include <cuda_fp16.h>
#include <math_constants.h>
#include <cstdint>

// Problem constants
#define NSEQ 2048
#define DMODEL 1024
#define NHEAD 16
#define HDIM 64
#define QKV_W (3 * DMODEL)   // 3072
#define QG_W  (4 * DMODEL)   // 4096

// ---------------------------------------------------------------------------
// Scratch (__device__ globals; no allocations allowed)
// ---------------------------------------------------------------------------
__device__ float  g_qkv [NSEQ * QKV_W];      // q|k|v, fp32
__device__ float  g_gate[NSEQ * DMODEL];     // sigmoid(x Wg^T + bg), fp32
__device__ __half g_attnh[NSEQ * DMODEL];    // (attn*gate), fp16
__device__ __half g_xh  [NSEQ * DMODEL];     // fp16 x
__device__ __half g_wqgh[QG_W * DMODEL];     // fp16 [Wqkv ; Wgate]
__device__ __half g_wouth[DMODEL * DMODEL];  // fp16 Wout

__device__ __forceinline__ float rna_tf32(float x) {
    float y;
    asm("cvt.rna.tf32.f32 %0, %1;" : "=f"(y) : "f"(x));
    return y;
}

// tf32 k8 mma (attention only)
__device__ __forceinline__ void mma16n8k8(float* c, const unsigned* a, const unsigned* b)
{
    asm volatile(
        "mma.sync.aligned.m16n8k8.row.col.f32.tf32.tf32.f32 "
        "{%0,%1,%2,%3}, {%4,%5,%6,%7}, {%8,%9}, {%0,%1,%2,%3};\n"
        : "+f"(c[0]), "+f"(c[1]), "+f"(c[2]), "+f"(c[3])
        : "r"(a[0]), "r"(a[1]), "r"(a[2]), "r"(a[3]), "r"(b[0]), "r"(b[1]));
}

// fp16 k16 mma (GEMMs)
__device__ __forceinline__ void mma16n8k16h(float* c, const unsigned* a, const unsigned* b)
{
    asm volatile(
        "mma.sync.aligned.m16n8k16.row.col.f32.f16.f16.f32 "
        "{%0,%1,%2,%3}, {%4,%5,%6,%7}, {%8,%9}, {%0,%1,%2,%3};\n"
        : "+f"(c[0]), "+f"(c[1]), "+f"(c[2]), "+f"(c[3])
        : "r"(a[0]), "r"(a[1]), "r"(a[2]), "r"(a[3]), "r"(b[0]), "r"(b[1]));
}

#define CP16(sm, gp) \
    asm volatile("cp.async.cg.shared.global [%0], [%1], 16;\n" :: "r"(sm), "l"(gp) : "memory")
#define CP_COMMIT() asm volatile("cp.async.commit_group;\n" ::: "memory")
#define CP_WAIT1()  asm volatile("cp.async.wait_group 1;\n" ::: "memory")

// ---------------------------------------------------------------------------
// Merged fp32->fp16 conversion: x | Wqkv | Wgate | Wout in ONE launch.
// Each thread: 2 float4 reads (32B), 1 uint4 write (16B) at half-offset j*4.
// ---------------------------------------------------------------------------
#define RS0 (NSEQ * DMODEL / 4)      // float4 counts (all even)
#define RS1 (QKV_W * DMODEL / 4)
#define RS2 (DMODEL * DMODEL / 4)
#define RS3 (DMODEL * DMODEL / 4)
#define CBLK 3584                    // (RS0+RS1+RS2+RS3)/2 / 256

__global__ void cvt_all(const float4* __restrict__ x,  __half* __restrict__ xh,
                        const float4* __restrict__ wq, __half* __restrict__ wqh,
                        const float4* __restrict__ wg, __half* __restrict__ wgh,
                        const float4* __restrict__ wo, __half* __restrict__ woh)
{
    const int i = blockIdx.x * 256 + threadIdx.x;   // uint4 output index
    int j = i * 2;                                  // float4 input index (even)
    const float4* src; __half* dst;
    if (j < RS0)               { src = x;  dst = xh; }
    else if ((j -= RS0) < RS1) { src = wq; dst = wqh; }
    else if ((j -= RS1) < RS2) { src = wg; dst = wgh; }
    else { j -= RS2;             src = wo; dst = woh; }
    const float4 v0 = src[j];
    const float4 v1 = src[j + 1];
    union { uint4 u; __half2 h[4]; } o;
    o.h[0] = __floats2half2_rn(v0.x, v0.y);
    o.h[1] = __floats2half2_rn(v0.z, v0.w);
    o.h[2] = __floats2half2_rn(v1.x, v1.y);
    o.h[3] = __floats2half2_rn(v1.z, v1.w);
    *(uint4*)(dst + (size_t)j * 4) = o.u;          // FIX: j*4 halves (was j*8)
}

// ---------------------------------------------------------------------------
// fp16 fused GEMM (qkv + gate): 256x128 CTA, 8 warps (4x2 of 64x64), BK=32
// halves, double-buffered cp.async. Smem rows: 32 halves data + 8 pad = 80 B
// (word stride 20 -> proven conflict-free fragment pattern).
// col0 < split -> C0/bias0 (linear); else C1/bias1 (sigmoid).
// ---------------------------------------------------------------------------
#define GBM 256
#define GBN 128
#define HLD 20                                  // 32-bit words per row
#define HSTGW ((GBM + GBN) * HLD)               // 7680 words / stage
#define HSMEM (2 * HSTGW * 4)                   // 61440 B

__global__ __launch_bounds__(256, 1)
void gemm_big(const __half* __restrict__ A, const __half* __restrict__ Wcat,
              const float* __restrict__ bias0, float* __restrict__ C0, int N0,
              const float* __restrict__ bias1, float* __restrict__ C1, int N1,
              int K, int split)
{
    extern __shared__ __align__(16) unsigned bsm[];

    const int tid  = threadIdx.x;
    const int lane = tid & 31;
    const int wid  = tid >> 5;
    const int wm   = wid & 3;
    const int wn   = wid >> 2;
    const int row0 = blockIdx.y * GBM;
    const int col0 = blockIdx.x * GBN;

    const int lr = tid >> 1;            // 0..127
    const int hs = (tid & 1) * 16;      // half offset within 32-half tile

    const __half* Ag  = A    + (size_t)(row0 + lr) * K + hs;
    const __half* Ag2 = Ag   + (size_t)128 * K;
    const __half* Wg  = Wcat + (size_t)(col0 + lr) * K + hs;

    const unsigned shb  = (unsigned)__cvta_generic_to_shared(bsm);
    const unsigned arow = lr * 80 + (tid & 1) * 32;
    const unsigned brow = GBM * 80 + arow;

    float acc[4][8][4];
#pragma unroll
    for (int mt = 0; mt < 4; mt++)
#pragma unroll
        for (int nt = 0; nt < 8; nt++)
#pragma unroll
            for (int i = 0; i < 4; i++) acc[mt][nt][i] = 0.0f;

    const int T = K / 32;

    // prologue
    {
        const unsigned sb = shb;
        CP16(sb + arow,                 Ag);
        CP16(sb + arow + 16,            Ag + 8);
        CP16(sb + arow + 128 * 80,      Ag2);
        CP16(sb + arow + 128 * 80 + 16, Ag2 + 8);
        CP16(sb + brow,                 Wg);
        CP16(sb + brow + 16,            Wg + 8);
    }
    CP_COMMIT();

    const int qk = lane & 3;
    const int qr = lane >> 2;

    for (int t = 0; t < T; t++) {
        const int buf = t & 1;
        if (t + 1 < T) {
            const unsigned sb = shb + (buf ^ 1) * (HSTGW * 4);
            const int k1 = (t + 1) * 32;
            CP16(sb + arow,                 Ag + k1);
            CP16(sb + arow + 16,            Ag + k1 + 8);
            CP16(sb + arow + 128 * 80,      Ag2 + k1);
            CP16(sb + arow + 128 * 80 + 16, Ag2 + k1 + 8);
            CP16(sb + brow,                 Wg + k1);
            CP16(sb + brow + 16,            Wg + k1 + 8);
        }
        CP_COMMIT();
        CP_WAIT1();
        __syncthreads();

        const unsigned* as = bsm + buf * HSTGW;
        const unsigned* bs = as + GBM * HLD;
#pragma unroll
        for (int ks = 0; ks < 2; ks++) {
            const int kw = ks * 8;
            unsigned bfr[8][2];
#pragma unroll
            for (int nt = 0; nt < 8; nt++) {
                const int n = wn * 64 + nt * 8 + qr;
                bfr[nt][0] = bs[n * HLD + kw + qk];
                bfr[nt][1] = bs[n * HLD + kw + qk + 4];
            }
            unsigned afr[4][4];
#pragma unroll
            for (int mt = 0; mt < 4; mt++) {
                const int m = wm * 64 + mt * 16 + qr;
                afr[mt][0] = as[m * HLD + kw + qk];
                afr[mt][1] = as[(m + 8) * HLD + kw + qk];
                afr[mt][2] = as[m * HLD + kw + qk + 4];
                afr[mt][3] = as[(m + 8) * HLD + kw + qk + 4];
            }
#pragma unroll
            for (int mt = 0; mt < 4; mt++)
#pragma unroll
                for (int nt = 0; nt < 8; nt++)
                    mma16n8k16h(acc[mt][nt], afr[mt], bfr[nt]);
        }
        __syncthreads();
    }

    const int second = (col0 >= split);
    const float* bias = second ? bias1 : bias0;
    float* C  = second ? C1 : C0;
    const int Nn = second ? N1 : N0;
    const int cb = col0 - (second ? split : 0);

#pragma unroll
    for (int mt = 0; mt < 4; mt++) {
        const int r0 = row0 + wm * 64 + mt * 16 + qr;
#pragma unroll
        for (int nt = 0; nt < 8; nt++) {
            const int c = cb + wn * 64 + nt * 8 + qk * 2;
            const float2 bv = *(const float2*)&bias[c];
            float v0 = acc[mt][nt][0] + bv.x;
            float v1 = acc[mt][nt][1] + bv.y;
            float v2 = acc[mt][nt][2] + bv.x;
            float v3 = acc[mt][nt][3] + bv.y;
            if (second) {
                v0 = 1.0f / (1.0f + __expf(-v0));
                v1 = 1.0f / (1.0f + __expf(-v1));
                v2 = 1.0f / (1.0f + __expf(-v2));
                v3 = 1.0f / (1.0f + __expf(-v3));
            }
            *(float2*)&C[(size_t)r0 * Nn + c]       = make_float2(v0, v1);
            *(float2*)&C[(size_t)(r0 + 8) * Nn + c] = make_float2(v2, v3);
        }
    }
}

// ---------------------------------------------------------------------------
// fp16 out-projection GEMM: 64x128 CTA, 4 warps (2x2 of 32x64), BK=32 halves,
// double-buffered cp.async, 3 CTAs/SM.
// ---------------------------------------------------------------------------
#define SBM 64
#define SBN 128

__global__ __launch_bounds__(128, 3)
void gemm_small(const __half* __restrict__ A, const __half* __restrict__ W,
                const float* __restrict__ bias, float* __restrict__ C, int Nn,
                int K)
{
    __shared__ __align__(16) unsigned Sh[2][(SBM + SBN) * HLD];   // 30720 B

    const int tid  = threadIdx.x;
    const int lane = tid & 31;
    const int wid  = tid >> 5;
    const int wm   = wid & 1;
    const int wn   = wid >> 1;
    const int row0 = blockIdx.y * SBM;
    const int col0 = blockIdx.x * SBN;

    const int lr = tid >> 1;            // 0..63
    const int hs = (tid & 1) * 16;

    const __half* Ag  = A + (size_t)(row0 + lr) * K + hs;
    const __half* Wg  = W + (size_t)(col0 + lr) * K + hs;
    const __half* Wg2 = Wg + (size_t)64 * K;

    const unsigned shb  = (unsigned)__cvta_generic_to_shared(&Sh[0][0]);
    const unsigned arow = lr * 80 + (tid & 1) * 32;
    const unsigned brow = SBM * 80 + arow;
    const unsigned stg  = (SBM + SBN) * HLD * 4;   // bytes per stage

    float acc[2][8][4];
#pragma unroll
    for (int mt = 0; mt < 2; mt++)
#pragma unroll
        for (int nt = 0; nt < 8; nt++)
#pragma unroll
            for (int i = 0; i < 4; i++) acc[mt][nt][i] = 0.0f;

    const int T = K / 32;

    {
        CP16(shb + arow,                Ag);
        CP16(shb + arow + 16,           Ag + 8);
        CP16(shb + brow,                Wg);
        CP16(shb + brow + 16,           Wg + 8);
        CP16(shb + brow + 64 * 80,      Wg2);
        CP16(shb + brow + 64 * 80 + 16, Wg2 + 8);
    }
    CP_COMMIT();

    const int qk = lane & 3;
    const int qr = lane >> 2;

    for (int t = 0; t < T; t++) {
        const int buf = t & 1;
        if (t + 1 < T) {
            const unsigned sb = shb + (buf ^ 1) * stg;
            const int k1 = (t + 1) * 32;
            CP16(sb + arow,                Ag + k1);
            CP16(sb + arow + 16,           Ag + k1 + 8);
            CP16(sb + brow,                Wg + k1);
            CP16(sb + brow + 16,           Wg + k1 + 8);
            CP16(sb + brow + 64 * 80,      Wg2 + k1);
            CP16(sb + brow + 64 * 80 + 16, Wg2 + k1 + 8);
        }
        CP_COMMIT();
        CP_WAIT1();
        __syncthreads();

        const unsigned* as = &Sh[buf][0];
        const unsigned* bs = as + SBM * HLD;
#pragma unroll
        for (int ks = 0; ks < 2; ks++) {
            const int kw = ks * 8;
            unsigned bfr[8][2];
#pragma unroll
            for (int nt = 0; nt < 8; nt++) {
                const int n = wn * 64 + nt * 8 + qr;
                bfr[nt][0] = bs[n * HLD + kw + qk];
                bfr[nt][1] = bs[n * HLD + kw + qk + 4];
            }
            unsigned afr[2][4];
#pragma unroll
            for (int mt = 0; mt < 2; mt++) {
                const int m = wm * 32 + mt * 16 + qr;
                afr[mt][0] = as[m * HLD + kw + qk];
                afr[mt][1] = as[(m + 8) * HLD + kw + qk];
                afr[mt][2] = as[m * HLD + kw + qk + 4];
                afr[mt][3] = as[(m + 8) * HLD + kw + qk + 4];
            }
#pragma unroll
            for (int mt = 0; mt < 2; mt++)
#pragma unroll
                for (int nt = 0; nt < 8; nt++)
                    mma16n8k16h(acc[mt][nt], afr[mt], bfr[nt]);
        }
        __syncthreads();
    }

#pragma unroll
    for (int mt = 0; mt < 2; mt++) {
        const int r0 = row0 + wm * 32 + mt * 16 + qr;
#pragma unroll
        for (int nt = 0; nt < 8; nt++) {
            const int c = col0 + wn * 64 + nt * 8 + qk * 2;
            const float2 bv = *(const float2*)&bias[c];
            *(float2*)&C[(size_t)r0 * Nn + c] =
                make_float2(acc[mt][nt][0] + bv.x, acc[mt][nt][1] + bv.y);
            *(float2*)&C[(size_t)(r0 + 8) * Nn + c] =
                make_float2(acc[mt][nt][2] + bv.x, acc[mt][nt][3] + bv.y);
        }
    }
}

// ---------------------------------------------------------------------------
// Block-cooperative attention (R11-R13 proven), tf32 tensor-core internals.
// Epilogue writes fp16 (out-proj A operand).
// ---------------------------------------------------------------------------
#define QT 16
#define NDENSE 65
#define WROWS 224
#define NTILES 28
#define KLD 68
#define SLD 228
#define ATTN_SMEM_BYTES 86080

__global__ __launch_bounds__(512, 2)
void attn_kernel(const float* __restrict__ qkv, const float* __restrict__ gate,
                 const float* __restrict__ pos_bias, const int* __restrict__ offsets,
                 __half* __restrict__ attn_out, int NO)
{
    extern __shared__ __align__(16) float dsm[];
    float* Qsh  = dsm;
    float* Ksh  = dsm + 1088;
    float* Ssh  = dsm + 16320;
    float* Gsh  = dsm + 19968;
    float* pb   = dsm + 21056;
    int*   goff = (int*)(dsm + 21136);
    int*   base = (int*)(dsm + 21216);
    int*   gidx = (int*)(dsm + 21296);

    const int tid = threadIdx.x;
    const int w = tid >> 5;
    const int l = tid & 31;
    const int h  = blockIdx.y;
    const int n0 = blockIdx.x * QT;

    if (tid < NO) {
        const int off = offsets[tid];
        goff[tid] = off;
        pb[tid]   = pos_bias[tid * NHEAD + h];
        base[tid] = (tid < NDENSE) ? (64 - off) : (80 + ((tid - NDENSE) << 4));
    }
    if (tid < WROWS) {
        int sn;
        if (tid < 80) sn = n0 - 64 + tid;
        else {
            const int g = (tid - 80) >> 4;
            const int s = (tid - 80) & 15;
            sn = (NDENSE + g < NO) ? (n0 - offsets[NDENSE + g] + s) : 0;
        }
        gidx[tid] = max(sn, 0);
    }
    __syncthreads();

    const float* Kg = qkv + DMODEL + h * HDIM;
    for (int i = tid; i < WROWS * 16; i += 512) {
        const int r  = i >> 4;
        const int c4 = (i & 15) << 2;
        const float4 v = *(const float4*)(Kg + (size_t)gidx[r] * QKV_W + c4);
        *(float4*)(Ksh + r * KLD + c4) =
            make_float4(rna_tf32(v.x), rna_tf32(v.y), rna_tf32(v.z), rna_tf32(v.w));
    }
    if (tid < 256) {
        const int r  = tid >> 4;
        const int c4 = (tid & 15) << 2;
        const float4 v = *(const float4*)(qkv + (size_t)(n0 + r) * QKV_W + h * HDIM + c4);
        *(float4*)(Qsh + r * KLD + c4) =
            make_float4(rna_tf32(v.x * 0.125f), rna_tf32(v.y * 0.125f),
                        rna_tf32(v.z * 0.125f), rna_tf32(v.w * 0.125f));
    } else {
        const int t2 = tid - 256;
        const int r  = t2 >> 4;
        const int c4 = (t2 & 15) << 2;
        *(float4*)(Gsh + r * KLD + c4) =
            *(const float4*)(gate + (size_t)(n0 + r) * DMODEL + h * HDIM + c4);
    }
    __syncthreads();

    const int qk = l & 3;
    const int qr = l >> 2;
    for (int nt = w; nt < NTILES; nt += 16) {
        float acc[4] = {0.0f, 0.0f, 0.0f, 0.0f};
#pragma unroll
        for (int ks = 0; ks < 8; ks++) {
            unsigned a[4], b[2];
            const float* qp = Qsh + qr * KLD + ks * 8 + qk;
            a[0] = __float_as_uint(qp[0]);
            a[1] = __float_as_uint(qp[8 * KLD]);
            a[2] = __float_as_uint(qp[4]);
            a[3] = __float_as_uint(qp[8 * KLD + 4]);
            const float* kp = Ksh + (nt * 8 + qr) * KLD + ks * 8 + qk;
            b[0] = __float_as_uint(kp[0]);
            b[1] = __float_as_uint(kp[4]);
            mma16n8k8(acc, a, b);
        }
        *(float2*)(Ssh + qr * SLD + nt * 8 + 2 * qk)       = make_float2(acc[0], acc[1]);
        *(float2*)(Ssh + (qr + 8) * SLD + nt * 8 + 2 * qk) = make_float2(acc[2], acc[3]);
    }
    __syncthreads();

    const float* Vg = qkv + 2 * DMODEL + h * HDIM;
    for (int i = tid; i < WROWS * 16; i += 512) {
        const int r  = i >> 4;
        const int c4 = (i & 15) << 2;
        const float4 v = *(const float4*)(Vg + (size_t)gidx[r] * QKV_W + c4);
        *(float4*)(Ksh + r * KLD + c4) =
            make_float4(rna_tf32(v.x), rna_tf32(v.y), rna_tf32(v.z), rna_tf32(v.w));
    }

    const int n = n0 + w;
    float* Srow = Ssh + w * SLD;
    float sloc[3];
    float m = -CUDART_INF_F;
#pragma unroll
    for (int j = 0; j < 3; j++) {
        const int o = l + 32 * j;
        float s = -CUDART_INF_F;
        if (o < NO && n - goff[o] >= 0)
            s = Srow[base[o] + w] + pb[o];
        sloc[j] = s;
        m = fmaxf(m, s);
    }
#pragma unroll
    for (int off = 16; off > 0; off >>= 1)
        m = fmaxf(m, __shfl_xor_sync(0xFFFFFFFFu, m, off));

    float ssum = 0.0f;
    float eloc[3];
#pragma unroll
    for (int j = 0; j < 3; j++) {
        const float e = (sloc[j] == -CUDART_INF_F) ? 0.0f : __expf(sloc[j] - m);
        eloc[j] = e;
        ssum += e;
    }
#pragma unroll
    for (int off = 16; off > 0; off >>= 1)
        ssum += __shfl_xor_sync(0xFFFFFFFFu, ssum, off);
    const float inv = 1.0f / ssum;

#pragma unroll
    for (int j = 0; j < 7; j++) Srow[l + 32 * j] = 0.0f;
    __syncwarp();
#pragma unroll
    for (int j = 0; j < 3; j++) {
        const int o = l + 32 * j;
        if (o < NO) Srow[base[o] + w] = rna_tf32(eloc[j] * inv);
    }
    __syncthreads();

    const int nt2 = w & 7;
    const int kh  = w >> 3;
    float facc[4] = {0.0f, 0.0f, 0.0f, 0.0f};
    for (int kk = kh * 14; kk < kh * 14 + 14; kk++) {
        unsigned a[4], b[2];
        const float* pp = Ssh + qr * SLD + kk * 8 + qk;
        a[0] = __float_as_uint(pp[0]);
        a[1] = __float_as_uint(pp[8 * SLD]);
        a[2] = __float_as_uint(pp[4]);
        a[3] = __float_as_uint(pp[8 * SLD + 4]);
        b[0] = __float_as_uint(Ksh[(kk * 8 + qk) * KLD + nt2 * 8 + qr]);
        b[1] = __float_as_uint(Ksh[(kk * 8 + qk + 4) * KLD + nt2 * 8 + qr]);
        mma16n8k8(facc, a, b);
    }

    if (kh == 1) {
        *(float2*)(Qsh + qr * KLD + nt2 * 8 + 2 * qk)       = make_float2(facc[0], facc[1]);
        *(float2*)(Qsh + (qr + 8) * KLD + nt2 * 8 + 2 * qk) = make_float2(facc[2], facc[3]);
    }
    __syncthreads();
    if (kh == 0) {
        const int cc = nt2 * 8 + 2 * qk;
        const float2 p0 = *(const float2*)(Qsh + qr * KLD + cc);
        const float2 p1 = *(const float2*)(Qsh + (qr + 8) * KLD + cc);
        const float2 g0 = *(const float2*)(Gsh + qr * KLD + cc);
        const float2 g1 = *(const float2*)(Gsh + (qr + 8) * KLD + cc);
        const __half2 r0 = __floats2half2_rn((facc[0] + p0.x) * g0.x,
                                             (facc[1] + p0.y) * g0.y);
        const __half2 r1 = __floats2half2_rn((facc[2] + p1.x) * g1.x,
                                             (facc[3] + p1.y) * g1.y);
        *(__half2*)(attn_out + (size_t)(n0 + qr) * DMODEL + h * HDIM + cc)     = r0;
        *(__half2*)(attn_out + (size_t)(n0 + qr + 8) * DMODEL + h * HDIM + cc) = r1;
    }
}

// ---------------------------------------------------------------------------
// Launch
// ---------------------------------------------------------------------------
extern "C" void kernel_launch(void* const* d_in, const int* in_sizes, int n_in,
                              void* d_out, int out_size)
{
    const float* x        = (const float*)d_in[0];
    const float* Wqkv     = (const float*)d_in[1];
    const float* bqkv     = (const float*)d_in[2];
    const float* Wgate    = (const float*)d_in[3];
    const float* bgate    = (const float*)d_in[4];
    const float* Wout     = (const float*)d_in[5];
    const float* bout     = (const float*)d_in[6];
    const float* pos_bias = (const float*)d_in[7];
    const int*   offsets  = (const int*)d_in[8];
    const int NO = in_sizes[8];

    float *qkv_p, *gate_p;
    __half *attnh_p, *xh_p, *wqgh_p, *wouth_p;
    cudaGetSymbolAddress((void**)&qkv_p,   g_qkv);
    cudaGetSymbolAddress((void**)&gate_p,  g_gate);
    cudaGetSymbolAddress((void**)&attnh_p, g_attnh);
    cudaGetSymbolAddress((void**)&xh_p,    g_xh);
    cudaGetSymbolAddress((void**)&wqgh_p,  g_wqgh);
    cudaGetSymbolAddress((void**)&wouth_p, g_wouth);

    cudaFuncSetAttribute(gemm_big, cudaFuncAttributeMaxDynamicSharedMemorySize,
                         HSMEM);
    cudaFuncSetAttribute(attn_kernel, cudaFuncAttributeMaxDynamicSharedMemorySize,
                         ATTN_SMEM_BYTES);

    // 0) fp32 -> fp16 conversion of all GEMM operands in ONE launch
    cvt_all<<<CBLK, 256>>>((const float4*)x,     xh_p,
                           (const float4*)Wqkv,  wqgh_p,
                           (const float4*)Wgate, wqgh_p + (size_t)QKV_W * DMODEL,
                           (const float4*)Wout,  wouth_p);

    // 1) fused: qkv = x@Wqkv^T+bqkv  AND  gate = sigmoid(x@Wgate^T+bgate)
    gemm_big<<<dim3(QG_W / GBN, NSEQ / GBM), 256, HSMEM>>>(
        xh_p, wqgh_p,
        bqkv,  qkv_p,  QKV_W,
        bgate, gate_p, DMODEL,
        DMODEL, QKV_W);

    // 2) attention + gate multiply (fp16 output)
    attn_kernel<<<dim3(NSEQ / QT, NHEAD), 512, ATTN_SMEM_BYTES>>>(
        qkv_p, gate_p, pos_bias, offsets, attnh_p, NO);

    // 3) out = (attn*gate) @ Wout^T + bout
    gemm_small<<<dim3(DMODEL / SBN, NSEQ / SBM), 128>>>(
        attnh_p, wouth_p, bout, (float*)d_out, DMODEL, DMODEL);
}